// round 10
// baseline (speedup 1.0000x reference)
#include <cuda_runtime.h>
#include <cuda_fp16.h>
#include <cstdint>

// ---------------------------------------------------------------------------
// out[512, 65536] = inputs[512,256] @ features[65536,256]^T   (fp32 in/out)
//
// Toolchain: compute_103 virtual arch -> no tcgen05; tensor path is
// ldmatrix + mma.sync.m16n8k16 (HMMA, plateaus at ~48% counter = roofline).
//
// Single fused kernel: B slabs are LDG'd as fp32 (L2-shared across the 4
// m_super CTAs), converted in registers, STS'd fp16 into ping-pong smem.
// R10 fix vs R9: staging reduced from 16 float4 (64 regs -> SPILLS, tensor
// fell to 39%) to 4 batches of 8 float4 (32 regs, issue at ks 1/5/9/13,
// consume 4 k-steps later) -- ~1Kcyc latency cover per batch, no spills.
//
// Structure: 148 CTAs x 256 threads, two independent 128-thread halves
// (named barriers), each half streams N=64 B slabs, warp tile 64x32,
// K=256 smem-resident A.
// ---------------------------------------------------------------------------

#define GY 37                            // grid (4, 37) = 148 CTAs (1/SM)
#define BLOCK 256
#define SMEM_BYTES (65536 + 4 * 32768)   // A 64KB + 2 halves x 2 x 32KB fp16

__device__ __forceinline__ uint32_t smem_u32(const void* p) {
    uint32_t a;
    asm("{ .reg .u64 t; cvta.to.shared.u64 t, %1; cvt.u32.u64 %0, t; }"
        : "=r"(a) : "l"(p));
    return a;
}

// Rows are 512B (256 halves). Swizzle: XOR 16B-chunk index with (row & 7).
__device__ __forceinline__ uint32_t swz(uint32_t off) {
    return off ^ (((off >> 9) & 7u) << 4);
}

__device__ __forceinline__ void ldm_x4(uint32_t* r, uint32_t addr) {
    asm volatile(
        "ldmatrix.sync.aligned.m8n8.x4.shared.b16 {%0,%1,%2,%3}, [%4];"
        : "=r"(r[0]), "=r"(r[1]), "=r"(r[2]), "=r"(r[3]) : "r"(addr));
}

__device__ __forceinline__ void mma_16816(float* c, const uint32_t* a,
                                          uint32_t b0, uint32_t b1) {
    asm volatile(
        "mma.sync.aligned.m16n8k16.row.col.f32.f16.f16.f32 "
        "{%0,%1,%2,%3}, {%4,%5,%6,%7}, {%8,%9}, {%0,%1,%2,%3};"
        : "+f"(c[0]), "+f"(c[1]), "+f"(c[2]), "+f"(c[3])
        : "r"(a[0]), "r"(a[1]), "r"(a[2]), "r"(a[3]), "r"(b0), "r"(b1));
}

__device__ __forceinline__ void stg_cs_v2(float* p, float x, float y) {
    asm volatile("st.global.cs.v2.f32 [%0], {%1, %2};"
                 :: "l"(p), "f"(x), "f"(y) : "memory");
}

// Convert one float4 to 4 halves and store 8B to swizzled smem.
__device__ __forceinline__ void cvt_sts(uint32_t smem_addr, float4 v) {
    __half2 h0 = __floats2half2_rn(v.x, v.y);
    __half2 h1 = __floats2half2_rn(v.z, v.w);
    asm volatile("st.shared.v2.b32 [%0], {%1, %2};"
                 :: "r"(smem_addr),
                    "r"(*reinterpret_cast<uint32_t*>(&h0)),
                    "r"(*reinterpret_cast<uint32_t*>(&h1)));
}

__global__ void __launch_bounds__(BLOCK, 1) gemm_kernel(
    const float* __restrict__ inputs,    // [512, 256]
    const float* __restrict__ features,  // [65536, 256]
    float* __restrict__ out)             // [512, 65536]
{
    extern __shared__ char smem[];
    const uint32_t sA = smem_u32(smem);                 // 64KB shared A fp16

    const int tid  = threadIdx.x;
    const int wid  = tid >> 5;
    const int lid  = tid & 31;
    const int half = wid >> 2;          // 0 or 1
    const int hw   = wid & 3;           // warp within half
    const int htid = tid & 127;
    const int wm   = hw >> 1;           // 0..1 (64 m-rows)
    const int wn   = hw & 1;            // 0..1 (32 n-rows)
    const int m_super = blockIdx.x;     // 0..3
    const int jb0 = blockIdx.y * 2 + half;   // slab stream: jb0 + k*74 < 1024

    const uint32_t sBh = sA + 65536u + (uint32_t)half * 65536u;  // 2x32KB

    // ---- Prologue: convert A stripe fp32 -> fp16 smem (whole CTA) ----
    {
        const float4* Ag = reinterpret_cast<const float4*>(inputs)
                         + m_super * 8192;
#pragma unroll 8
        for (int it = 0; it < 32; ++it) {
            int fi = it * 256 + tid;           // coalesced
            float4 v = __ldg(Ag + fi);
            int row = fi >> 6;                 // 64 float4 per 256-half row
            int c4  = fi & 63;
            cvt_sts(sA + swz((uint32_t)(row * 512 + c4 * 8)), v);
        }
    }
    // ---- Prologue: convert this half's first B slab into buffer 0 ----
    {
        const float4* Bg = reinterpret_cast<const float4*>(features)
                         + (size_t)jb0 * 4096;
#pragma unroll 8
        for (int it = 0; it < 32; ++it) {
            int fi = it * 128 + htid;
            float4 v = __ldg(Bg + fi);
            int row = fi >> 6;
            int c4  = fi & 63;
            cvt_sts(sBh + swz((uint32_t)(row * 512 + c4 * 8)), v);
        }
    }
    __syncthreads();   // A visible CTA-wide; each half's slab 0 in place

    // Per-lane ldmatrix address components
    const int a_row = lid & 15;
    const int a_kb  = (lid >> 4) * 16;
    const int b_row = (lid & 7) + ((lid >> 4) * 8);
    const int b_kb  = ((lid >> 3) & 1) * 16;
    const int bar_id = 1 + half;
    // Per-thread STS placement for converted B float4s:
    //   it = batch*8 + r covers row = it*2 + (htid>>6), c4 = htid&63
    const int srow = htid >> 6;          // 0..1
    const int sc4  = htid & 63;

    int parity = 0;
    for (int jb = jb0; jb < 1024; jb += 74) {
        const bool has_nxt = (jb + 74) < 1024;
        const float4* src = reinterpret_cast<const float4*>(features)
                          + (size_t)(jb + 74) * 4096;
        const uint32_t sBc = sBh + (uint32_t)parity * 32768u;        // compute
        const uint32_t sBn = sBh + (uint32_t)(parity ^ 1) * 32768u;  // fill

        float acc[4][4][4];
#pragma unroll
        for (int mf = 0; mf < 4; ++mf)
#pragma unroll
            for (int nf = 0; nf < 4; ++nf)
#pragma unroll
                for (int e = 0; e < 4; ++e) acc[mf][nf][e] = 0.0f;

        float4 stage[8];   // one 8-float4 batch in flight (32 regs)

#pragma unroll
        for (int ks = 0; ks < 16; ++ks) {
            // Staged fp32 LDG -> cvt/STS pipeline for the NEXT slab:
            // issue batch b at ks==1+4b, consume it 4 k-steps later.
            if (has_nxt && (ks & 3) == 1) {
                const int b = ks >> 2;          // batch being issued: 0..3
                if (b > 0) {
#pragma unroll
                    for (int r = 0; r < 8; ++r) {   // consume batch b-1
                        int it = (b - 1) * 8 + r;
                        uint32_t off =
                            (uint32_t)((it * 2 + srow) * 512 + sc4 * 8);
                        cvt_sts(sBn + swz(off), stage[r]);
                    }
                }
#pragma unroll
                for (int r = 0; r < 8; ++r)
                    stage[r] = __ldg(src + (b * 8 + r) * 128 + htid);
            }

            const uint32_t kb = (uint32_t)ks * 32;
            uint32_t a[4][4];
#pragma unroll
            for (int mf = 0; mf < 4; ++mf) {
                int row = wm * 64 + mf * 16 + a_row;
                ldm_x4(a[mf], sA + swz((uint32_t)(row * 512) + kb + a_kb));
            }
            uint32_t b[2][4];
#pragma unroll
            for (int ng = 0; ng < 2; ++ng) {
                int nrow = wn * 32 + ng * 16 + b_row;
                ldm_x4(b[ng], sBc + swz((uint32_t)(nrow * 512) + kb + b_kb));
            }
#pragma unroll
            for (int mf = 0; mf < 4; ++mf)
#pragma unroll
                for (int nf = 0; nf < 4; ++nf)
                    mma_16816(acc[mf][nf], a[mf],
                              b[nf >> 1][(nf & 1) * 2 + 0],
                              b[nf >> 1][(nf & 1) * 2 + 1]);
        }

        // Consume the final batch (3) into the fill buffer.
        if (has_nxt) {
#pragma unroll
            for (int r = 0; r < 8; ++r) {
                int it = 24 + r;
                uint32_t off = (uint32_t)((it * 2 + srow) * 512 + sc4 * 8);
                cvt_sts(sBn + swz(off), stage[r]);
            }
        }

        // Epilogue: streaming GMEM float2 stores
        const int row0 = m_super * 128 + wm * 64 + (lid >> 2);
        const int col0 = jb * 64 + wn * 32 + (lid & 3) * 2;
#pragma unroll
        for (int mf = 0; mf < 4; ++mf) {
#pragma unroll
            for (int nf = 0; nf < 4; ++nf) {
                const int r = row0 + mf * 16;
                const int c = col0 + nf * 8;
                stg_cs_v2(out + (size_t)r * 65536 + c,
                          acc[mf][nf][0], acc[mf][nf][1]);
                stg_cs_v2(out + (size_t)(r + 8) * 65536 + c,
                          acc[mf][nf][2], acc[mf][nf][3]);
            }
        }

        // Half-local barrier: all 4 warps done reading sBc and writing sBn.
        asm volatile("bar.sync %0, 128;" :: "r"(bar_id) : "memory");
        parity ^= 1;
    }
}

extern "C" void kernel_launch(void* const* d_in, const int* in_sizes, int n_in,
                              void* d_out, int out_size) {
    // metadata order: inputs f32[512,256], indexes i64[512],
    //                 features f32[65536,256], mIoU f32[65536], IoU f32[512];
    //                 output f32[512,65536]
    const float* inputs   = (const float*)d_in[0];
    const float* features = (const float*)d_in[2];
    float* out = (float*)d_out;

    cudaFuncSetAttribute(gemm_kernel,
                         cudaFuncAttributeMaxDynamicSharedMemorySize, SMEM_BYTES);
    // grid.x = m_super (fast): the 4 CTAs sharing each B slab run concurrently
    gemm_kernel<<<dim3(4, GY), BLOCK, SMEM_BYTES>>>(inputs, features, out);
}